// round 1
// baseline (speedup 1.0000x reference)
#include <cuda_runtime.h>
#include <cuda_bf16.h>

#define DIM 128
#define TEMP_INV (1.0f / 0.07f)

// Flag set by the detection kernel: 1 if index buffers are int64, 0 if int32.
__device__ int g_idx_is64;

// Values in the index tensors are uniform in [0, 1e6) -> fit in 20 bits.
// If stored as little-endian int64, every odd 32-bit word is zero.
// If stored as int32, the odd-position words are themselves random indices;
// P(64 of them all zero) ~ (1e-6)^64 ~ 0.
__global__ void detect_idx_kernel(const unsigned int* __restrict__ idx_words) {
    if (threadIdx.x == 0) {
        unsigned int acc = 0;
#pragma unroll
        for (int i = 1; i < 128; i += 2) acc |= idx_words[i];
        g_idx_is64 = (acc == 0) ? 1 : 0;
    }
}

__global__ __launch_bounds__(256, 8)
void la_loss_kernel(const float* __restrict__ codes,
                    const float* __restrict__ bank,
                    const void* __restrict__ idx_bg,
                    const void* __restrict__ idx_cl,
                    float* __restrict__ out,
                    int K)
{
    const int b    = blockIdx.x;
    const int tid  = threadIdx.x;
    const int wid  = tid >> 5;      // 0..7
    const int lane = tid & 31;
    const bool is64 = (g_idx_is64 != 0);

    // ---- load this batch row's code vector and normalize (per-warp, no smem) ----
    // lane l holds elements [4l, 4l+4) of the 128-dim vector.
    float4 c4 = reinterpret_cast<const float4*>(codes + (size_t)b * DIM)[lane];
    float ss = c4.x * c4.x + c4.y * c4.y + c4.z * c4.z + c4.w * c4.w;
#pragma unroll
    for (int o = 16; o; o >>= 1) ss += __shfl_xor_sync(0xffffffffu, ss, o);
    const float rn = rsqrtf(ss);
    const float4 v4 = make_float4(c4.x * rn, c4.y * rn, c4.z * rn, c4.w * rn);

    // warps 0-3 -> background indices, warps 4-7 -> close indices
    const void* idx = (wid < 4) ? idx_bg : idx_cl;
    const int wsub = wid & 3;   // 0..3 within the group of 4 warps
    const size_t base = (size_t)b * (size_t)K;

    float acc = 0.0f;
#pragma unroll 2
    for (int n = wsub; n < K; n += 4) {
        long long ii;
        if (is64) ii = reinterpret_cast<const long long*>(idx)[base + n];
        else      ii = (long long)reinterpret_cast<const int*>(idx)[base + n];

        // one fully-coalesced 512B row load per warp
        float4 r = reinterpret_cast<const float4*>(bank + (size_t)ii * DIM)[lane];
        float d = r.x * v4.x + r.y * v4.y + r.z * v4.z + r.w * v4.w;
#pragma unroll
        for (int o = 16; o; o >>= 1) d += __shfl_xor_sync(0xffffffffu, d, o);
        acc += __expf(d * TEMP_INV);
    }

    __shared__ float s[8];
    if (lane == 0) s[wid] = acc;
    __syncthreads();
    if (tid == 0) {
        float d1 = s[0] + s[1] + s[2] + s[3];
        float d2 = s[4] + s[5] + s[6] + s[7];
        out[b] = logf(d1) - logf(d2);
    }
}

extern "C" void kernel_launch(void* const* d_in, const int* in_sizes, int n_in,
                              void* d_out, int out_size) {
    const float* codes = (const float*)d_in[0];
    const float* bank  = (const float*)d_in[1];
    const void*  ibg   = d_in[2];
    const void*  icl   = d_in[3];
    float* out = (float*)d_out;

    const int B = out_size;                 // 1024
    const int K = in_sizes[2] / B;          // 200 (element count regardless of dtype)

    detect_idx_kernel<<<1, 32>>>((const unsigned int*)ibg);
    la_loss_kernel<<<B, 256>>>(codes, bank, ibg, icl, out, K);
}